// round 10
// baseline (speedup 1.0000x reference)
#include <cuda_runtime.h>

// AdvectionDiffusionReaction2M — temporal-blocked stencil, S=4 chunks.
// Ext 64x32, owned 56x24, block (16,8)=256 thr (4x4 cells/thread), grid
// 10x22=220 blocks, 50 launches (49x4 + 1x3).
// R4-R9 model: time = instr_volume / (SMs * issue_rate); issue_rate needs
// >1 block/SM; S=4 cuts halo so more blocks come with LOWER redundancy
// (1.52x vs R4's 1.78x). Per-cell arithmetic identical to R4.

#define NN     512
#define N2     (NN * NN)
#define S      4
#define OWNW   56
#define OWNH   24
#define EXTW   64
#define EXTH   32
#define NSTEPS 199

template <int NS>
__global__ __launch_bounds__(256)
void adr_chunk_kernel(const float* __restrict__ src,
                      float*       __restrict__ out,
                      int t0,
                      const float* __restrict__ k1p,
                      const float* __restrict__ k2p,
                      const float* __restrict__ a1p,
                      const float* __restrict__ a2p)
{
    // double-buffered strip-boundary rows; strip ty+1, pads at 0 and 9
    __shared__ float s_top[2][10][EXTW];
    __shared__ float s_bot[2][10][EXTW];

    const int tx = threadIdx.x;   // 0..15, cols 4tx..4tx+3 of ext tile
    const int ty = threadIdx.y;   // 0..7,  rows 4ty..4ty+3

    const int ro0 = blockIdx.y * OWNH;   // by: 0..21 (last truncated at 512)
    const int co0 = blockIdx.x * OWNW;   // bx: 0..9  (last truncated at 512)
    const int gi0 = ro0 - S + 4 * ty;
    const int gj0 = co0 - S + 4 * tx;

    // zero pad rows once (read by ty==0 / ty==7; affects rim cells only)
    if (ty == 0) {
        #pragma unroll
        for (int q = 0; q < 4; ++q) {
            s_top[0][0][tx + 16 * q] = 0.f; s_top[0][9][tx + 16 * q] = 0.f;
            s_top[1][0][tx + 16 * q] = 0.f; s_top[1][9][tx + 16 * q] = 0.f;
            s_bot[0][0][tx + 16 * q] = 0.f; s_bot[0][9][tx + 16 * q] = 0.f;
            s_bot[1][0][tx + 16 * q] = 0.f; s_bot[1][9][tx + 16 * q] = 0.f;
        }
    }

    const float k1 = __ldg(k1p), k2 = __ldg(k2p);
    const float a1 = __ldg(a1p), a2 = __ldg(a2p);
    const float inv_ksum = 1.0f / (k1 + k2);

    const float dx2f   = (float)((1.0 / 511.0) * (1.0 / 511.0));
    const float twodxf = (float)(2.0 / 511.0);
    const float DT     = 1e-7f;

    // 4-col packs never straddle j=256 (256-(co0-4) = 260-56bx divisible by 4)
    const float kap  = (gj0 < 256) ? k1 : k2;
    const float al   = (gj0 < 256) ? a1 : a2;
    const float c_al = DT * al / dx2f;
    const float cx   = DT * kap / twodxf;
    const float ck   = DT * kap;

    // ---- clamped initial load (field at step t0-1) ----
    float v[4][4];
    #pragma unroll
    for (int r = 0; r < 4; ++r) {
        const int gi = min(max(gi0 + r, 0), NN - 1);
        #pragma unroll
        for (int c = 0; c < 4; ++c) {
            const int gj = min(max(gj0 + c, 0), NN - 1);
            v[r][c] = src[gi * NN + gj];
        }
    }

    // intra-thread fixup / ownership flags (derived for this geometry)
    const bool ifc    = (gj0 + 3 == 255);                  // bx==4, tx==8
    const bool fix_rt = (blockIdx.y == 0  && ty == 1);     // row 0   <- row 1  : n[0]<-n[1]
    const bool fix_rb = (blockIdx.y == 21 && ty == 2);     // row 511 <- row 510: n[3]<-n[2]
    const bool fix_cl = (blockIdx.x == 0  && tx == 1);     // col 0   <- col 1  : c0<-c1
    const bool fix_cr = (blockIdx.x == 9  && tx == 2);     // col 511 <- col 510: c3<-c2
    const bool store_ok = (ty >= 1 && ty < 7) &&
                          (tx >= 1 && tx < 15) &&
                          (gi0 < NN) && (gj0 < NN);

    float* __restrict__ slab = out + (size_t)t0 * N2;
    const unsigned FULL = 0xffffffffu;
    __syncthreads();   // pads visible before first level

    #pragma unroll
    for (int k = 0; k < NS; ++k) {
        const int pb = k & 1;

        // ---- vertical boundary exchange (old values, 16B ops) ----
        *(float4*)&s_top[pb][ty + 1][4 * tx] = make_float4(v[0][0], v[0][1], v[0][2], v[0][3]);
        *(float4*)&s_bot[pb][ty + 1][4 * tx] = make_float4(v[3][0], v[3][1], v[3][2], v[3][3]);
        __syncthreads();
        const float4 upv = *(const float4*)&s_bot[pb][ty][4 * tx];       // row above strip
        const float4 dnv = *(const float4*)&s_top[pb][ty + 2][4 * tx];   // row below strip
        const float up[4] = {upv.x, upv.y, upv.z, upv.w};
        const float dn[4] = {dnv.x, dnv.y, dnv.z, dnv.w};

        // ---- horizontal pack edges (old values). Warp spans 2 ty rows; the
        // cross-row shfl at tx=0/15 only feeds rim packs (garbage-by-design,
        // margin exactly S). ----
        float lft[4], rgt[4];
        #pragma unroll
        for (int r = 0; r < 4; ++r) {
            lft[r] = __shfl_up_sync(FULL,   v[r][3], 1);
            rgt[r] = __shfl_down_sync(FULL, v[r][0], 1);
        }

        // ---- 16 cell updates (identical arithmetic to round 4) ----
        float n[4][4];
        #pragma unroll
        for (int r = 0; r < 4; ++r) {
            #pragma unroll
            for (int c = 0; c < 4; ++c) {
                const float cu = v[r][c];
                const float u_ = (r == 0) ? up[c] : v[r - 1][c];
                const float d_ = (r == 3) ? dn[c] : v[r + 1][c];
                const float l_ = (c == 0) ? lft[r] : v[r][c - 1];
                const float r_ = (c == 3) ? rgt[r] : v[r][c + 1];

                const float sum  = (u_ + d_) + (l_ + r_);
                const float lap  = fmaf(-4.0f, cu, sum);
                const float A    = fmaf(cu, d_ - u_, l_ - r_);
                const float adv  = cu * A;
                const float q    = fmaf(cu, cu, -cu);
                const float reac = cu * (q + 1.0f);

                float val = fmaf(c_al, lap, cu);
                val = fmaf(-cx, adv, val);
                val = fmaf(ck, reac, val);
                n[r][c] = val;
            }
        }

        // ---- interface column j=255 (bx==4, tx==8, c==3), OLD neighbors ----
        if (ifc) {
            #pragma unroll
            for (int r = 0; r < 4; ++r)
                n[r][3] = (k1 * rgt[r] + k2 * v[r][2]) * inv_ksum;
        }

        // ---- domain-edge fixups (rows then cols, matching reference order) ----
        if (fix_rt) { n[0][0] = n[1][0]; n[0][1] = n[1][1]; n[0][2] = n[1][2]; n[0][3] = n[1][3]; }
        if (fix_rb) { n[3][0] = n[2][0]; n[3][1] = n[2][1]; n[3][2] = n[2][2]; n[3][3] = n[2][3]; }
        if (fix_cl) { n[0][0] = n[0][1]; n[1][0] = n[1][1]; n[2][0] = n[2][1]; n[3][0] = n[3][1]; }
        if (fix_cr) { n[0][3] = n[0][2]; n[1][3] = n[1][2]; n[2][3] = n[2][2]; n[3][3] = n[3][2]; }

        // ---- store owned 4x4 (coalesced 16B stores) ----
        if (store_ok) {
            #pragma unroll
            for (int r = 0; r < 4; ++r)
                *(float4*)&slab[(size_t)(gi0 + r) * NN + gj0] =
                    make_float4(n[r][0], n[r][1], n[r][2], n[r][3]);
        }

        slab += N2;
        #pragma unroll
        for (int r = 0; r < 4; ++r)
            #pragma unroll
            for (int c = 0; c < 4; ++c)
                v[r][c] = n[r][c];
    }
}

extern "C" void kernel_launch(void* const* d_in, const int* in_sizes, int n_in,
                              void* d_out, int out_size)
{
    const float* u0  = (const float*)d_in[0];
    const float* k1p = (const float*)d_in[1];
    const float* k2p = (const float*)d_in[2];
    const float* a1p = (const float*)d_in[3];
    const float* a2p = (const float*)d_in[4];
    float* out = (float*)d_out;

    dim3 block(16, 8, 1);
    dim3 grid((NN + OWNW - 1) / OWNW, (NN + OWNH - 1) / OWNH, 1);  // 10 x 22 = 220

    int t0 = 0;
    for (int c = 0; c < 49; ++c) {
        const float* src = (t0 == 0) ? u0 : (out + (size_t)(t0 - 1) * N2);
        adr_chunk_kernel<4><<<grid, block>>>(src, out, t0, k1p, k2p, a1p, a2p);
        t0 += 4;
    }
    {
        const float* src = out + (size_t)(t0 - 1) * N2;
        adr_chunk_kernel<3><<<grid, block>>>(src, out, t0, k1p, k2p, a1p, a2p);
    }
}

// round 11
// speedup vs baseline: 1.7066x; 1.7066x over previous
#include <cuda_runtime.h>

// AdvectionDiffusionReaction2M — temporal-blocked stencil (champion R4 geometry)
// + Programmatic Dependent Launch to collapse inter-chunk serialization.
//
// R4/R10 measurement: fixed ~2.5us per serialized graph node (ramp+drain+gap),
// 25 nodes -> ~60us of the 133us total. PDL overlaps the next chunk's CTA
// dispatch/prologue with the current chunk's tail:
//   - consumer: setup (indices/flags/scalar loads) BEFORE
//     cudaGridDependencySynchronize(); src reads after.
//   - producer: cudaTriggerProgrammaticLaunchCompletion() after level 0.
// Geometry (validated rounds 4/7): ext 64x64, owned 48x48, 4x4 cells/thread,
// block (16,16), grid 11x11=121, S=8, 25 launches, redundancy 1.78x.

#define NN     512
#define N2     (NN * NN)
#define S      8
#define TILEW  48
#define EXT    64
#define NSTEPS 199

template <int NS>
__global__ __launch_bounds__(256)
void adr_chunk_kernel(const float* __restrict__ src,
                      float*       __restrict__ out,
                      int t0,
                      const float* __restrict__ k1p,
                      const float* __restrict__ k2p,
                      const float* __restrict__ a1p,
                      const float* __restrict__ a2p)
{
    // double-buffered strip-boundary rows; strip ty+1, pads at 0 and 17
    __shared__ float s_top[2][18][EXT];
    __shared__ float s_bot[2][18][EXT];

    const int tx = threadIdx.x;   // 0..15, cols 4tx..4tx+3 of ext tile
    const int ty = threadIdx.y;   // 0..15, rows 4ty..4ty+3

    const int ro0 = blockIdx.y * TILEW;
    const int co0 = blockIdx.x * TILEW;
    const int gi0 = ro0 - S + 4 * ty;
    const int gj0 = co0 - S + 4 * tx;

    // -------- prologue independent of the producer chunk --------
    const float k1 = __ldg(k1p), k2 = __ldg(k2p);        // harness inputs, not produced in-graph
    const float a1 = __ldg(a1p), a2 = __ldg(a2p);
    const float inv_ksum = 1.0f / (k1 + k2);

    const float dx2f   = (float)((1.0 / 511.0) * (1.0 / 511.0));
    const float twodxf = (float)(2.0 / 511.0);
    const float DT     = 1e-7f;

    // 4-col packs never straddle j=256
    const float kap  = (gj0 < 256) ? k1 : k2;
    const float al   = (gj0 < 256) ? a1 : a2;
    const float c_al = DT * al / dx2f;
    const float cx   = DT * kap / twodxf;
    const float ck   = DT * kap;

    // fixup / ownership flags (validated round 4)
    const bool ifc      = (gj0 + 3 == 255);
    const bool fix_rt   = (blockIdx.y == 0  && ty == 2);   // row 0   <- row 1
    const bool fix_rb   = (ro0 == 480       && ty == 9);   // row 511 <- row 510
    const bool fix_cl   = (blockIdx.x == 0  && tx == 2);   // col 0   <- col 1
    const bool fix_cr   = (co0 == 480       && tx == 9);   // col 511 <- col 510
    const bool store_ok = (tx >= 2 && tx < 14 && ty >= 2 && ty < 14 &&
                           gi0 < NN && gj0 < NN);

    const unsigned FULL = 0xffffffffu;

    // -------- wait for producer chunk to fully complete --------
    cudaGridDependencySynchronize();

    // ---- clamped initial load (field at step t0-1) ----
    float v[4][4];
    #pragma unroll
    for (int r = 0; r < 4; ++r) {
        const int gi = min(max(gi0 + r, 0), NN - 1);
        #pragma unroll
        for (int c = 0; c < 4; ++c) {
            const int gj = min(max(gj0 + c, 0), NN - 1);
            v[r][c] = src[gi * NN + gj];
        }
    }

    float* __restrict__ slab = out + (size_t)t0 * N2;

    #pragma unroll
    for (int k = 0; k < NS; ++k) {
        const int pb = k & 1;

        // ---- vertical boundary exchange (old values, 16B ops) ----
        *(float4*)&s_top[pb][ty + 1][4 * tx] = make_float4(v[0][0], v[0][1], v[0][2], v[0][3]);
        *(float4*)&s_bot[pb][ty + 1][4 * tx] = make_float4(v[3][0], v[3][1], v[3][2], v[3][3]);
        __syncthreads();
        const float4 upv = *(const float4*)&s_bot[pb][ty][4 * tx];       // row above strip
        const float4 dnv = *(const float4*)&s_top[pb][ty + 2][4 * tx];   // row below strip
        const float up[4] = {upv.x, upv.y, upv.z, upv.w};
        const float dn[4] = {dnv.x, dnv.y, dnv.z, dnv.w};

        // ---- horizontal pack edges (old values) ----
        float lft[4], rgt[4];
        #pragma unroll
        for (int r = 0; r < 4; ++r) {
            lft[r] = __shfl_up_sync(FULL,   v[r][3], 1);
            rgt[r] = __shfl_down_sync(FULL, v[r][0], 1);
        }

        // ---- 16 cell updates ----
        float n[4][4];
        #pragma unroll
        for (int r = 0; r < 4; ++r) {
            #pragma unroll
            for (int c = 0; c < 4; ++c) {
                const float cu = v[r][c];
                const float u_ = (r == 0) ? up[c] : v[r - 1][c];
                const float d_ = (r == 3) ? dn[c] : v[r + 1][c];
                const float l_ = (c == 0) ? lft[r] : v[r][c - 1];
                const float r_ = (c == 3) ? rgt[r] : v[r][c + 1];

                const float sum  = (u_ + d_) + (l_ + r_);
                const float lap  = fmaf(-4.0f, cu, sum);
                const float A    = fmaf(cu, d_ - u_, l_ - r_);
                const float adv  = cu * A;
                const float q    = fmaf(cu, cu, -cu);
                const float reac = cu * (q + 1.0f);

                float val = fmaf(c_al, lap, cu);
                val = fmaf(-cx, adv, val);
                val = fmaf(ck, reac, val);
                n[r][c] = val;
            }
        }

        // ---- interface column j=255 (c==3 of tx==5), from OLD neighbors ----
        if (ifc) {
            #pragma unroll
            for (int r = 0; r < 4; ++r)
                n[r][3] = (k1 * rgt[r] + k2 * v[r][2]) * inv_ksum;
        }

        // ---- domain-edge fixups (rows then cols, matching reference order) ----
        if (fix_rt) { n[0][0] = n[1][0]; n[0][1] = n[1][1]; n[0][2] = n[1][2]; n[0][3] = n[1][3]; }
        if (fix_rb) { n[3][0] = n[2][0]; n[3][1] = n[2][1]; n[3][2] = n[2][2]; n[3][3] = n[2][3]; }
        if (fix_cl) { n[0][0] = n[0][1]; n[1][0] = n[1][1]; n[2][0] = n[2][1]; n[3][0] = n[3][1]; }
        if (fix_cr) { n[0][3] = n[0][2]; n[1][3] = n[1][2]; n[2][3] = n[2][2]; n[3][3] = n[3][2]; }

        // ---- store owned 4x4 (coalesced 16B stores) ----
        if (store_ok) {
            #pragma unroll
            for (int r = 0; r < 4; ++r)
                *(float4*)&slab[(size_t)(gi0 + r) * NN + gj0] =
                    make_float4(n[r][0], n[r][1], n[r][2], n[r][3]);
        }

        slab += N2;
        #pragma unroll
        for (int r = 0; r < 4; ++r)
            #pragma unroll
            for (int c = 0; c < 4; ++c)
                v[r][c] = n[r][c];

        // ---- after first level: allow the next chunk's CTAs to launch ----
        if (k == 0)
            cudaTriggerProgrammaticLaunchCompletion();
    }
}

template <int NS>
static void launch_chunk(const float* src, float* out, int t0,
                         const float* k1p, const float* k2p,
                         const float* a1p, const float* a2p)
{
    dim3 block(16, 16, 1);
    dim3 grid((NN + TILEW - 1) / TILEW, (NN + TILEW - 1) / TILEW, 1);  // 11 x 11

    cudaLaunchAttribute attr[1];
    attr[0].id = cudaLaunchAttributeProgrammaticStreamSerialization;
    attr[0].val.programmaticStreamSerializationAllowed = 1;

    cudaLaunchConfig_t cfg = {};
    cfg.gridDim = grid;
    cfg.blockDim = block;
    cfg.dynamicSmemBytes = 0;
    cfg.stream = 0;                 // legacy default stream (same as <<<>>>)
    cfg.attrs = attr;
    cfg.numAttrs = 1;

    cudaLaunchKernelEx(&cfg, adr_chunk_kernel<NS>,
                       src, out, t0, k1p, k2p, a1p, a2p);
}

extern "C" void kernel_launch(void* const* d_in, const int* in_sizes, int n_in,
                              void* d_out, int out_size)
{
    const float* u0  = (const float*)d_in[0];
    const float* k1p = (const float*)d_in[1];
    const float* k2p = (const float*)d_in[2];
    const float* a1p = (const float*)d_in[3];
    const float* a2p = (const float*)d_in[4];
    float* out = (float*)d_out;

    int t0 = 0;
    for (int c = 0; c < 24; ++c) {
        const float* src = (t0 == 0) ? u0 : (out + (size_t)(t0 - 1) * N2);
        launch_chunk<8>(src, out, t0, k1p, k2p, a1p, a2p);
        t0 += 8;
    }
    {
        const float* src = out + (size_t)(t0 - 1) * N2;
        launch_chunk<7>(src, out, t0, k1p, k2p, a1p, a2p);
    }
}